// round 15
// baseline (speedup 1.0000x reference)
#include <cuda_runtime.h>
#include <cuda_bf16.h>
#include <cstdint>
#include <math.h>

// Problem constants
#define BB 4
#define TT 2048
#define CC 1024
#define NH 16
#define HD 64
#define MM (BB * TT)          // 8192 tokens
#define EPSV 1e-5f

// -------------------- scratch (static device globals; no allocation) --------
__device__ float          g_x1 [MM * CC];         // residual after attention (fp32)
__device__ __nv_bfloat16  g_lnh[MM * CC],      g_lnl[MM * CC];       // LN out split
__device__ __nv_bfloat16  g_yh [MM * CC],      g_yl [MM * CC];       // attn out split
__device__ __nv_bfloat16  g_hh [MM * 4 * CC],  g_hl [MM * 4 * CC];   // gelu(fc) split
// q/k/v split bf16, layout [bh][t][d]  (bh = b*16+h)
__device__ __nv_bfloat16  g_qh [MM * CC], g_ql [MM * CC];
__device__ __nv_bfloat16  g_kh [MM * CC], g_kl [MM * CC];
__device__ __nv_bfloat16  g_vh [MM * CC], g_vl [MM * CC];
// transposed + split weights: Wt[N,K]
__device__ __nv_bfloat16  g_wah[3 * CC * CC],  g_wal[3 * CC * CC];   // w_attn^T
__device__ __nv_bfloat16  g_wph[CC * CC],      g_wpl[CC * CC];       // w_proj^T
__device__ __nv_bfloat16  g_wfh[4 * CC * CC],  g_wfl[4 * CC * CC];   // w_fc^T
__device__ __nv_bfloat16  g_w2h[CC * 4 * CC],  g_w2l[CC * 4 * CC];   // w_fc2^T

// ---------------------------------------------------------------------------
// Baseline-ISA helpers (sm_80+: cp.async, ldmatrix, mma.sync — NO tcgen05)
// ---------------------------------------------------------------------------
__device__ __forceinline__ uint32_t smem_u32(const void* p) {
    uint32_t a;
    asm("{ .reg .u64 t; cvta.to.shared.u64 t, %1; cvt.u32.u64 %0, t; }" : "=r"(a) : "l"(p));
    return a;
}

#define CP16(dst, src) \
    asm volatile("cp.async.cg.shared.global [%0], [%1], 16;" :: "r"(dst), "l"(src))
#define CP_COMMIT() asm volatile("cp.async.commit_group;")
#define CP_WAIT1()  asm volatile("cp.async.wait_group 1;")

__device__ __forceinline__ void ldsm_x4(uint32_t* r, uint32_t addr) {
    asm volatile("ldmatrix.sync.aligned.m8n8.x4.shared.b16 {%0,%1,%2,%3}, [%4];"
                 : "=r"(r[0]), "=r"(r[1]), "=r"(r[2]), "=r"(r[3]) : "r"(addr));
}
__device__ __forceinline__ void ldsm_x4_t(uint32_t* r, uint32_t addr) {
    asm volatile("ldmatrix.sync.aligned.m8n8.x4.trans.shared.b16 {%0,%1,%2,%3}, [%4];"
                 : "=r"(r[0]), "=r"(r[1]), "=r"(r[2]), "=r"(r[3]) : "r"(addr));
}

__device__ __forceinline__ void mma_bf16(float* d, const uint32_t* a, const uint32_t* b) {
    asm volatile(
        "mma.sync.aligned.m16n8k16.row.col.f32.bf16.bf16.f32 "
        "{%0,%1,%2,%3}, {%4,%5,%6,%7}, {%8,%9}, {%0,%1,%2,%3};"
        : "+f"(d[0]), "+f"(d[1]), "+f"(d[2]), "+f"(d[3])
        : "r"(a[0]), "r"(a[1]), "r"(a[2]), "r"(a[3]), "r"(b[0]), "r"(b[1]));
}

__device__ __forceinline__ void split2(float v, __nv_bfloat16& hi, __nv_bfloat16& lo) {
    hi = __float2bfloat16(v);
    lo = __float2bfloat16(v - __bfloat162float(hi));
}

// ---------------------------------------------------------------------------
// Weight transpose + split: W[K,N] fp32 -> Th[N,K], Tl[N,K] bf16
// ---------------------------------------------------------------------------
__global__ __launch_bounds__(256) void wsplit_t(
    const float* __restrict__ W, __nv_bfloat16* __restrict__ Th,
    __nv_bfloat16* __restrict__ Tl, int K, int N)
{
    __shared__ float t[32][33];
    const int tx = threadIdx.x, ty = threadIdx.y;
    const int n0 = blockIdx.x * 32, k0 = blockIdx.y * 32;
    #pragma unroll
    for (int i = 0; i < 4; i++)
        t[ty + i * 8][tx] = W[(size_t)(k0 + ty + i * 8) * N + n0 + tx];
    __syncthreads();
    #pragma unroll
    for (int i = 0; i < 4; i++) {
        float v = t[tx][ty + i * 8];
        __nv_bfloat16 hi, lo;
        split2(v, hi, lo);
        size_t idx = (size_t)(n0 + ty + i * 8) * K + k0 + tx;
        Th[idx] = hi;
        Tl[idx] = lo;
    }
}

// ---------------------------------------------------------------------------
// LayerNorm -> split bf16 hi/lo. One block per row, 256 threads, float4/thread.
// ---------------------------------------------------------------------------
__global__ __launch_bounds__(256) void ln_split(
    const float* __restrict__ x, const float* __restrict__ g,
    const float* __restrict__ b,
    __nv_bfloat16* __restrict__ oh, __nv_bfloat16* __restrict__ ol)
{
    __shared__ float red[8];
    __shared__ float s_mu, s_rstd;
    const int row = blockIdx.x;
    const int tid = threadIdx.x;
    const float4 v = ((const float4*)(x + (size_t)row * CC))[tid];

    float sum = v.x + v.y + v.z + v.w;
    #pragma unroll
    for (int o = 16; o; o >>= 1) sum += __shfl_xor_sync(0xffffffffu, sum, o);
    if ((tid & 31) == 0) red[tid >> 5] = sum;
    __syncthreads();
    if (tid < 8) {
        float t = red[tid];
        #pragma unroll
        for (int o = 4; o; o >>= 1) t += __shfl_xor_sync(0xffu, t, o);
        if (tid == 0) s_mu = t * (1.0f / CC);
    }
    __syncthreads();
    const float mu = s_mu;

    float dx = v.x - mu, dy = v.y - mu, dz = v.z - mu, dw = v.w - mu;
    float sq = dx * dx + dy * dy + dz * dz + dw * dw;
    #pragma unroll
    for (int o = 16; o; o >>= 1) sq += __shfl_xor_sync(0xffffffffu, sq, o);
    __syncthreads();
    if ((tid & 31) == 0) red[tid >> 5] = sq;
    __syncthreads();
    if (tid < 8) {
        float t = red[tid];
        #pragma unroll
        for (int o = 4; o; o >>= 1) t += __shfl_xor_sync(0xffu, t, o);
        if (tid == 0) s_rstd = rsqrtf(t * (1.0f / CC) + EPSV);
    }
    __syncthreads();
    const float rstd = s_rstd;

    const float4 gg = ((const float4*)g)[tid];
    const float4 bb = ((const float4*)b)[tid];
    float o0 = dx * rstd * gg.x + bb.x;
    float o1 = dy * rstd * gg.y + bb.y;
    float o2 = dz * rstd * gg.z + bb.z;
    float o3 = dw * rstd * gg.w + bb.w;

    __nv_bfloat162 h01, h23, l01, l23;
    split2(o0, h01.x, l01.x); split2(o1, h01.y, l01.y);
    split2(o2, h23.x, l23.x); split2(o3, h23.y, l23.y);
    size_t idx = (size_t)row * CC + tid * 4;
    *(__nv_bfloat162*)&oh[idx]     = h01;
    *(__nv_bfloat162*)&oh[idx + 2] = h23;
    *(__nv_bfloat162*)&ol[idx]     = l01;
    *(__nv_bfloat162*)&ol[idx + 2] = l23;
}

// ---------------------------------------------------------------------------
// Split-bf16 HMMA GEMM: C[M,N] = (Ah+Al)[M,K] @ (Bh+Bl)[N,K]^T (+epilogue)
// 128x128 CTA tile, BK=64 chunks, 3-stage cp.async pipeline, ONE barrier/chunk.
// 8 warps: warp_m = wid&3 (32 rows each), warp_n = wid>>2 (64 cols each).
// ---------------------------------------------------------------------------
enum { EPI_F32 = 0, EPI_F32_RES = 1, EPI_GELU_BF16 = 2, EPI_QKV = 3 };

__device__ __forceinline__ float gelu_tanh(float x) {
    float x3 = x * x * x;
    float t = tanhf(0.7978845608028654f * (x + 0.044715f * x3));
    return 0.5f * x * (1.0f + t);
}

#define RS 144                    // smem row stride bytes (64 bf16 + 8 pad)
#define TILE_B (128 * RS)         // 18432 B per tile
#define STAGE_B (4 * TILE_B)      // Ah, Al, Bh, Bl = 73728
#define NSTAGE 3
#define GEMM_SMEM_BYTES (NSTAGE * STAGE_B)   // 221184

template <int EPI>
__global__ __launch_bounds__(256, 1) void gemm_tc(
    const __nv_bfloat16* __restrict__ Ah, const __nv_bfloat16* __restrict__ Al,
    const __nv_bfloat16* __restrict__ Bh, const __nv_bfloat16* __restrict__ Bl,
    const float* __restrict__ bias, const float* __restrict__ res,
    float* __restrict__ Cf, __nv_bfloat16* __restrict__ Chi,
    __nv_bfloat16* __restrict__ Clo,
    __nv_bfloat16* __restrict__ Qh, __nv_bfloat16* __restrict__ Ql,
    __nv_bfloat16* __restrict__ Kh, __nv_bfloat16* __restrict__ Kl,
    __nv_bfloat16* __restrict__ Vh, __nv_bfloat16* __restrict__ Vl,
    int M, int N, int K)
{
    extern __shared__ __align__(1024) char dsm[];
    const uint32_t smem = smem_u32(dsm);

    const int tid   = threadIdx.x;
    const int lane  = tid & 31;
    const int wid   = tid >> 5;
    const int warp_m = wid & 3;
    const int warp_n = wid >> 2;
    const int row0 = blockIdx.y * 128;
    const int col0 = blockIdx.x * 128;

    // ---- load mapping: row = tid>>1, 64B half per thread (4 x CP16) ------
    const int lrow = tid >> 1;
    const int half = tid & 1;                 // 0 or 1 (32 bf16 = 64 B each)
    const __nv_bfloat16* pAh = Ah + (size_t)(row0 + lrow) * K + half * 32;
    const __nv_bfloat16* pAl = Al + (size_t)(row0 + lrow) * K + half * 32;
    const __nv_bfloat16* pBh = Bh + (size_t)(col0 + lrow) * K + half * 32;
    const __nv_bfloat16* pBl = Bl + (size_t)(col0 + lrow) * K + half * 32;
    const uint32_t dbase = smem + lrow * RS + half * 64;

    const int nk = K >> 6;     // BK=64 chunks

    auto load_stage = [&](int i) {
        const uint32_t d = dbase + (i % NSTAGE) * STAGE_B;
        const int k0 = i * 64;
        #pragma unroll
        for (int s = 0; s < 4; s++) {
            CP16(d + s * 16,              pAh + k0 + s * 8);
            CP16(d + TILE_B + s * 16,     pAl + k0 + s * 8);
            CP16(d + 2 * TILE_B + s * 16, pBh + k0 + s * 8);
            CP16(d + 3 * TILE_B + s * 16, pBl + k0 + s * 8);
        }
    };

    float acc[2][8][4];
    #pragma unroll
    for (int i = 0; i < 2; i++)
        #pragma unroll
        for (int j = 0; j < 8; j++)
            #pragma unroll
            for (int q = 0; q < 4; q++) acc[i][j][q] = 0.0f;

    // ldmatrix address components (within a stage)
    const uint32_t a_off = smem + (warp_m * 32 + (lane & 15)) * RS + ((lane >> 4) << 4);
    const uint32_t b_off = smem + 2 * TILE_B
                         + (warp_n * 64 + (lane & 7) + ((lane >> 4) & 1) * 8) * RS
                         + (((lane >> 3) & 1) << 4);

    // ---- prologue ---------------------------------------------------------
    load_stage(0); CP_COMMIT();
    load_stage(1); CP_COMMIT();

    for (int i = 0; i < nk; i++) {
        CP_WAIT1();
        __syncthreads();               // stage i ready; protects stage (i%3) rewrite
        if (i + 2 < nk) load_stage(i + 2);
        CP_COMMIT();

        const uint32_t sb = (uint32_t)((i % NSTAGE) * STAGE_B);
        #pragma unroll
        for (int ks = 0; ks < 4; ks++) {       // four k16 slices of BK=64
            uint32_t ah[2][4], al[2][4], bh[8][2], bl[8][2];
            #pragma unroll
            for (int mf = 0; mf < 2; mf++) {
                uint32_t ra = a_off + sb + mf * 16 * RS + ks * 32;
                ldsm_x4(ah[mf], ra);
                ldsm_x4(al[mf], ra + TILE_B);
            }
            #pragma unroll
            for (int p = 0; p < 4; p++) {
                uint32_t rb = b_off + sb + p * 16 * RS + ks * 32;
                uint32_t t[4];
                ldsm_x4(t, rb);
                bh[2 * p][0] = t[0]; bh[2 * p][1] = t[1];
                bh[2 * p + 1][0] = t[2]; bh[2 * p + 1][1] = t[3];
                ldsm_x4(t, rb + TILE_B);
                bl[2 * p][0] = t[0]; bl[2 * p][1] = t[1];
                bl[2 * p + 1][0] = t[2]; bl[2 * p + 1][1] = t[3];
            }
            #pragma unroll
            for (int mf = 0; mf < 2; mf++)
                #pragma unroll
                for (int j = 0; j < 8; j++) {
                    mma_bf16(acc[mf][j], ah[mf], bh[j]);
                    mma_bf16(acc[mf][j], ah[mf], bl[j]);
                    mma_bf16(acc[mf][j], al[mf], bh[j]);
                }
        }
    }

    // ---- epilogue ---------------------------------------------------------
    #pragma unroll
    for (int mf = 0; mf < 2; mf++) {
        const int rbase = row0 + warp_m * 32 + mf * 16 + (lane >> 2);
        #pragma unroll
        for (int h = 0; h < 2; h++) {
            const int r = rbase + h * 8;
            const size_t rowoff = (size_t)r * N;
            #pragma unroll
            for (int j = 0; j < 8; j++) {
                const int c = col0 + warp_n * 64 + j * 8 + (lane & 3) * 2;
                float o0 = acc[mf][j][h * 2 + 0] + bias[c + 0];
                float o1 = acc[mf][j][h * 2 + 1] + bias[c + 1];
                if (EPI == EPI_F32_RES) {
                    const float2 rv = *(const float2*)&res[rowoff + c];
                    o0 += rv.x; o1 += rv.y;
                    *(float2*)&Cf[rowoff + c] = make_float2(o0, o1);
                } else if (EPI == EPI_GELU_BF16) {
                    o0 = gelu_tanh(o0); o1 = gelu_tanh(o1);
                    __nv_bfloat162 hx, lx;
                    split2(o0, hx.x, lx.x); split2(o1, hx.y, lx.y);
                    *(__nv_bfloat162*)&Chi[rowoff + c] = hx;
                    *(__nv_bfloat162*)&Clo[rowoff + c] = lx;
                } else if (EPI == EPI_QKV) {
                    const int sec = c >> 10;            // 0=q 1=k 2=v
                    const int ci  = c & 1023;
                    const int hh_ = ci >> 6, d = ci & 63;
                    if (sec == 0) { o0 *= 0.125f; o1 *= 0.125f; }
                    const size_t idx =
                        ((size_t)((r >> 11) * NH + hh_) * TT + (r & 2047)) * HD + d;
                    __nv_bfloat162 hx, lx;
                    split2(o0, hx.x, lx.x); split2(o1, hx.y, lx.y);
                    __nv_bfloat16* dh = (sec == 0) ? Qh : (sec == 1) ? Kh : Vh;
                    __nv_bfloat16* dl = (sec == 0) ? Ql : (sec == 1) ? Kl : Vl;
                    *(__nv_bfloat162*)&dh[idx] = hx;
                    *(__nv_bfloat162*)&dl[idx] = lx;
                } else {
                    *(float2*)&Cf[rowoff + c] = make_float2(o0, o1);
                }
            }
        }
    }
}

// ---------------------------------------------------------------------------
// HMMA flash attention (FA2-style, split-bf16 3-pass QK and PV, fp32 softmax)
// Grid (T/128, B*NH), 256 threads = 8 warps x 16 q-rows.
// ---------------------------------------------------------------------------
#define AT_RS 144                      // 72 bf16 per row (conflict-free ldmatrix)
#define AT_Q_BYTES (128 * AT_RS)       // 18432 per tensor
#define AT_KV_T    (64 * AT_RS)        // 9216 per tensor
#define AT_STG     (4 * AT_KV_T)       // kh,kl,vh,vl = 36864
#define AT_SMEM    (2 * AT_Q_BYTES + 2 * AT_STG)   // 110592

__global__ __launch_bounds__(256, 1) void attn_mma(
    const __nv_bfloat16* __restrict__ qh_g, const __nv_bfloat16* __restrict__ ql_g,
    const __nv_bfloat16* __restrict__ kh_g, const __nv_bfloat16* __restrict__ kl_g,
    const __nv_bfloat16* __restrict__ vh_g, const __nv_bfloat16* __restrict__ vl_g,
    __nv_bfloat16* __restrict__ yh, __nv_bfloat16* __restrict__ yl)
{
    extern __shared__ __align__(1024) char sm[];
    const uint32_t smem = smem_u32(sm);
    const int qt = blockIdx.x;
    const int bh = blockIdx.y;
    const int b = bh >> 4, h = bh & 15;
    const int tid = threadIdx.x, lane = tid & 31, w = tid >> 5;

    const uint32_t SQH = smem, SQL = smem + AT_Q_BYTES, SKV = smem + 2 * AT_Q_BYTES;
    const size_t gbase = (size_t)bh * TT * HD;

    auto load_kv = [&](int kt, int s) {
        const uint32_t dst0 = SKV + s * AT_STG;
        #pragma unroll
        for (int rep = 0; rep < 2; rep++) {
            int ch = rep * 256 + tid;          // 0..511
            int row = ch >> 3, c = ch & 7;
            size_t go = gbase + (size_t)(kt * 64 + row) * HD + c * 8;
            uint32_t d = dst0 + row * AT_RS + c * 16;
            CP16(d,               kh_g + go);
            CP16(d + AT_KV_T,     kl_g + go);
            CP16(d + 2 * AT_KV_T, vh_g + go);
            CP16(d + 3 * AT_KV_T, vl_g + go);
        }
    };

    // prologue: Q (both) + KV tile 0 in group 0
    {
        #pragma unroll
        for (int rep = 0; rep < 4; rep++) {
            int ch = rep * 256 + tid;          // 0..1023
            int row = ch >> 3, c = ch & 7;
            size_t go = gbase + (size_t)(qt * 128 + row) * HD + c * 8;
            CP16(SQH + row * AT_RS + c * 16, qh_g + go);
            CP16(SQL + row * AT_RS + c * 16, ql_g + go);
        }
        load_kv(0, 0);
        CP_COMMIT();
    }

    float O[8][4];
    #pragma unroll
    for (int j = 0; j < 8; j++)
        #pragma unroll
        for (int q = 0; q < 4; q++) O[j][q] = 0.0f;
    float m0 = -1e30f, m1 = -1e30f, l0 = 0.0f, l1 = 0.0f;
    uint32_t qfh[4][4], qfl[4][4];

    const int ktmax = 2 * qt + 1;
    const int r0g = qt * 128 + w * 16 + (lane >> 2);

    for (int kt = 0; kt <= ktmax; kt++) {
        if (kt + 1 <= ktmax) load_kv(kt + 1, (kt + 1) & 1);
        CP_COMMIT();
        CP_WAIT1();
        __syncthreads();

        if (kt == 0) {
            const uint32_t aq = (w * 16 + (lane & 15)) * AT_RS + ((lane >> 4) << 4);
            #pragma unroll
            for (int kk = 0; kk < 4; kk++) {
                ldsm_x4(qfh[kk], SQH + aq + kk * 32);
                ldsm_x4(qfl[kk], SQL + aq + kk * 32);
            }
        }

        const uint32_t kh_s = SKV + (kt & 1) * AT_STG;
        const uint32_t kl_s = kh_s + AT_KV_T;
        const uint32_t vh_s = kh_s + 2 * AT_KV_T;
        const uint32_t vl_s = kh_s + 3 * AT_KV_T;

        // ---- S = Q K^T (3-pass) ------------------------------------------
        float S[8][4];
        #pragma unroll
        for (int j = 0; j < 8; j++)
            #pragma unroll
            for (int q = 0; q < 4; q++) S[j][q] = 0.0f;

        const uint32_t brow = ((lane & 7) + ((lane >> 4) & 1) * 8) * AT_RS
                            + (((lane >> 3) & 1) << 4);
        #pragma unroll
        for (int kk = 0; kk < 4; kk++) {
            uint32_t bhf[8][2], blf[8][2];
            #pragma unroll
            for (int p = 0; p < 4; p++) {
                uint32_t t4[4];
                uint32_t ad = brow + p * 16 * AT_RS + kk * 32;
                ldsm_x4(t4, kh_s + ad);
                bhf[2 * p][0] = t4[0]; bhf[2 * p][1] = t4[1];
                bhf[2 * p + 1][0] = t4[2]; bhf[2 * p + 1][1] = t4[3];
                ldsm_x4(t4, kl_s + ad);
                blf[2 * p][0] = t4[0]; blf[2 * p][1] = t4[1];
                blf[2 * p + 1][0] = t4[2]; blf[2 * p + 1][1] = t4[3];
            }
            #pragma unroll
            for (int j = 0; j < 8; j++) {
                mma_bf16(S[j], qfh[kk], bhf[j]);
                mma_bf16(S[j], qfh[kk], blf[j]);
                mma_bf16(S[j], qfl[kk], bhf[j]);
            }
        }

        // ---- causal mask (only tiles kt >= 2*qt can cross the diagonal) --
        if (kt >= 2 * qt) {
            #pragma unroll
            for (int j = 0; j < 8; j++) {
                int key = kt * 64 + j * 8 + (lane & 3) * 2;
                if (key     > r0g)     S[j][0] = -1e30f;
                if (key + 1 > r0g)     S[j][1] = -1e30f;
                if (key     > r0g + 8) S[j][2] = -1e30f;
                if (key + 1 > r0g + 8) S[j][3] = -1e30f;
            }
        }

        // ---- online softmax ----------------------------------------------
        float mx0 = -1e30f, mx1 = -1e30f;
        #pragma unroll
        for (int j = 0; j < 8; j++) {
            mx0 = fmaxf(mx0, fmaxf(S[j][0], S[j][1]));
            mx1 = fmaxf(mx1, fmaxf(S[j][2], S[j][3]));
        }
        mx0 = fmaxf(mx0, __shfl_xor_sync(0xffffffffu, mx0, 1));
        mx0 = fmaxf(mx0, __shfl_xor_sync(0xffffffffu, mx0, 2));
        mx1 = fmaxf(mx1, __shfl_xor_sync(0xffffffffu, mx1, 1));
        mx1 = fmaxf(mx1, __shfl_xor_sync(0xffffffffu, mx1, 2));
        float mn0 = fmaxf(m0, mx0), mn1 = fmaxf(m1, mx1);
        float sc0 = __expf(m0 - mn0), sc1 = __expf(m1 - mn1);
        m0 = mn0; m1 = mn1;
        l0 *= sc0; l1 *= sc1;
        #pragma unroll
        for (int j = 0; j < 8; j++) {
            O[j][0] *= sc0; O[j][1] *= sc0; O[j][2] *= sc1; O[j][3] *= sc1;
            S[j][0] = __expf(S[j][0] - mn0);
            S[j][1] = __expf(S[j][1] - mn0);
            S[j][2] = __expf(S[j][2] - mn1);
            S[j][3] = __expf(S[j][3] - mn1);
            l0 += S[j][0] + S[j][1];
            l1 += S[j][2] + S[j][3];
        }

        // ---- O += P V (3-pass) -------------------------------------------
        #pragma unroll
        for (int kk = 0; kk < 4; kk++) {
            uint32_t ph[4], pl[4];
            #pragma unroll
            for (int u = 0; u < 2; u++) {
                int j = 2 * kk + u;
                __nv_bfloat162 hA, lA, hB, lB;
                split2(S[j][0], hA.x, lA.x); split2(S[j][1], hA.y, lA.y);
                split2(S[j][2], hB.x, lB.x); split2(S[j][3], hB.y, lB.y);
                ph[0 + u * 2] = *(uint32_t*)&hA;
                ph[1 + u * 2] = *(uint32_t*)&hB;
                pl[0 + u * 2] = *(uint32_t*)&lA;
                pl[1 + u * 2] = *(uint32_t*)&lB;
            }
            const uint32_t vrow = (kk * 16 + (lane & 15)) * AT_RS + ((lane >> 4) << 4);
            #pragma unroll
            for (int dp = 0; dp < 4; dp++) {
                uint32_t t4[4];
                uint32_t ad = vrow + dp * 32;
                ldsm_x4_t(t4, vh_s + ad);
                mma_bf16(O[2 * dp],     ph, t4);
                mma_bf16(O[2 * dp + 1], ph, t4 + 2);
                mma_bf16(O[2 * dp],     pl, t4);
                mma_bf16(O[2 * dp + 1], pl, t4 + 2);
                ldsm_x4_t(t4, vl_s + ad);
                mma_bf16(O[2 * dp],     ph, t4);
                mma_bf16(O[2 * dp + 1], ph, t4 + 2);
            }
        }
        __syncthreads();
    }

    // ---- finalize + write y split bf16 -----------------------------------
    l0 += __shfl_xor_sync(0xffffffffu, l0, 1);
    l0 += __shfl_xor_sync(0xffffffffu, l0, 2);
    l1 += __shfl_xor_sync(0xffffffffu, l1, 1);
    l1 += __shfl_xor_sync(0xffffffffu, l1, 2);
    const float inv0 = 1.0f / l0, inv1 = 1.0f / l1;

    const size_t yb0 = (size_t)(b * TT + qt * 128 + w * 16 + (lane >> 2)) * CC + h * HD;
    const size_t yb1 = yb0 + (size_t)8 * CC;
    #pragma unroll
    for (int j = 0; j < 8; j++) {
        const int d = j * 8 + (lane & 3) * 2;
        __nv_bfloat162 hx, lx;
        split2(O[j][0] * inv0, hx.x, lx.x);
        split2(O[j][1] * inv0, hx.y, lx.y);
        *(__nv_bfloat162*)&yh[yb0 + d] = hx;
        *(__nv_bfloat162*)&yl[yb0 + d] = lx;
        split2(O[j][2] * inv1, hx.x, lx.x);
        split2(O[j][3] * inv1, hx.y, lx.y);
        *(__nv_bfloat162*)&yh[yb1 + d] = hx;
        *(__nv_bfloat162*)&yl[yb1 + d] = lx;
    }
}

// ---------------------------------------------------------------------------
extern "C" void kernel_launch(void* const* d_in, const int* in_sizes, int n_in,
                              void* d_out, int out_size)
{
    const float* x      = (const float*)d_in[0];
    const float* ln1_g  = (const float*)d_in[1];
    const float* ln1_b  = (const float*)d_in[2];
    const float* w_attn = (const float*)d_in[3];
    const float* b_attn = (const float*)d_in[4];
    const float* w_proj = (const float*)d_in[5];
    const float* b_proj = (const float*)d_in[6];
    const float* ln2_g  = (const float*)d_in[7];
    const float* ln2_b  = (const float*)d_in[8];
    const float* w_fc   = (const float*)d_in[9];
    const float* b_fc   = (const float*)d_in[10];
    const float* w_fc2  = (const float*)d_in[11];
    const float* b_fc2  = (const float*)d_in[12];
    float* out = (float*)d_out;

    float *x1p;
    __nv_bfloat16 *lnh, *lnl, *yh, *yl, *hh, *hl;
    __nv_bfloat16 *qh, *ql, *kh, *kl, *vh, *vl;
    __nv_bfloat16 *wah, *wal, *wph, *wpl, *wfh, *wfl, *w2h, *w2l;
    cudaGetSymbolAddress((void**)&x1p,  g_x1);
    cudaGetSymbolAddress((void**)&lnh,  g_lnh);  cudaGetSymbolAddress((void**)&lnl, g_lnl);
    cudaGetSymbolAddress((void**)&yh,   g_yh);   cudaGetSymbolAddress((void**)&yl,  g_yl);
    cudaGetSymbolAddress((void**)&hh,   g_hh);   cudaGetSymbolAddress((void**)&hl,  g_hl);
    cudaGetSymbolAddress((void**)&qh,   g_qh);   cudaGetSymbolAddress((void**)&ql,  g_ql);
    cudaGetSymbolAddress((void**)&kh,   g_kh);   cudaGetSymbolAddress((void**)&kl,  g_kl);
    cudaGetSymbolAddress((void**)&vh,   g_vh);   cudaGetSymbolAddress((void**)&vl,  g_vl);
    cudaGetSymbolAddress((void**)&wah,  g_wah);  cudaGetSymbolAddress((void**)&wal, g_wal);
    cudaGetSymbolAddress((void**)&wph,  g_wph);  cudaGetSymbolAddress((void**)&wpl, g_wpl);
    cudaGetSymbolAddress((void**)&wfh,  g_wfh);  cudaGetSymbolAddress((void**)&wfl, g_wfl);
    cudaGetSymbolAddress((void**)&w2h,  g_w2h);  cudaGetSymbolAddress((void**)&w2l, g_w2l);

    cudaFuncSetAttribute(gemm_tc<EPI_QKV>,       cudaFuncAttributeMaxDynamicSharedMemorySize, GEMM_SMEM_BYTES);
    cudaFuncSetAttribute(gemm_tc<EPI_F32_RES>,   cudaFuncAttributeMaxDynamicSharedMemorySize, GEMM_SMEM_BYTES);
    cudaFuncSetAttribute(gemm_tc<EPI_GELU_BF16>, cudaFuncAttributeMaxDynamicSharedMemorySize, GEMM_SMEM_BYTES);
    cudaFuncSetAttribute(attn_mma, cudaFuncAttributeMaxDynamicSharedMemorySize, AT_SMEM);

    const dim3 tb(32, 8);
    wsplit_t<<<dim3(3 * CC / 32, CC / 32), tb>>>(w_attn, wah, wal, CC, 3 * CC);
    wsplit_t<<<dim3(CC / 32, CC / 32), tb>>>(w_proj, wph, wpl, CC, CC);
    wsplit_t<<<dim3(4 * CC / 32, CC / 32), tb>>>(w_fc, wfh, wfl, CC, 4 * CC);
    wsplit_t<<<dim3(CC / 32, 4 * CC / 32), tb>>>(w_fc2, w2h, w2l, 4 * CC, CC);

    // 1) LN1
    ln_split<<<MM, 256>>>(x, ln1_g, ln1_b, lnh, lnl);
    // 2) qkv GEMM -> split q(scaled)/k/v bf16 in [bh][t][d]
    gemm_tc<EPI_QKV><<<dim3(3 * CC / 128, MM / 128), 256, GEMM_SMEM_BYTES>>>(
        lnh, lnl, wah, wal, b_attn, nullptr, nullptr, nullptr, nullptr,
        qh, ql, kh, kl, vh, vl, MM, 3 * CC, CC);
    // 3) HMMA flash attention -> y split
    attn_mma<<<dim3(TT / 128, BB * NH), 256, AT_SMEM>>>(qh, ql, kh, kl, vh, vl, yh, yl);
    // 4) x1 = x + y @ w_proj + b_proj
    gemm_tc<EPI_F32_RES><<<dim3(CC / 128, MM / 128), 256, GEMM_SMEM_BYTES>>>(
        yh, yl, wph, wpl, b_proj, x, x1p, nullptr, nullptr,
        nullptr, nullptr, nullptr, nullptr, nullptr, nullptr, MM, CC, CC);
    // 5) LN2
    ln_split<<<MM, 256>>>(x1p, ln2_g, ln2_b, lnh, lnl);
    // 6) hfc = gelu(ln @ w_fc + b_fc) -> split bf16
    gemm_tc<EPI_GELU_BF16><<<dim3(4 * CC / 128, MM / 128), 256, GEMM_SMEM_BYTES>>>(
        lnh, lnl, wfh, wfl, b_fc, nullptr, nullptr, hh, hl,
        nullptr, nullptr, nullptr, nullptr, nullptr, nullptr, MM, 4 * CC, CC);
    // 7) out = x1 + hfc @ w_fc2 + b_fc2
    gemm_tc<EPI_F32_RES><<<dim3(CC / 128, MM / 128), 256, GEMM_SMEM_BYTES>>>(
        hh, hl, w2h, w2l, b_fc2, x1p, out, nullptr, nullptr,
        nullptr, nullptr, nullptr, nullptr, nullptr, nullptr, MM, CC, 4 * CC);
}

// round 16
// speedup vs baseline: 1.7383x; 1.7383x over previous
#include <cuda_runtime.h>
#include <cuda_bf16.h>
#include <cstdint>
#include <math.h>

// Problem constants
#define BB 4
#define TT 2048
#define CC 1024
#define NH 16
#define HD 64
#define MM (BB * TT)          // 8192 tokens
#define EPSV 1e-5f

// -------------------- scratch (static device globals; no allocation) --------
__device__ float          g_x1 [MM * CC];         // residual after attention (fp32)
__device__ __nv_bfloat16  g_lnh[MM * CC],      g_lnl[MM * CC];       // LN out split
__device__ __nv_bfloat16  g_yh [MM * CC],      g_yl [MM * CC];       // attn out split
__device__ __nv_bfloat16  g_hh [MM * 4 * CC],  g_hl [MM * 4 * CC];   // gelu(fc) split
// q/k/v split bf16, layout [bh][t][d]  (bh = b*16+h)
__device__ __nv_bfloat16  g_qh [MM * CC], g_ql [MM * CC];
__device__ __nv_bfloat16  g_kh [MM * CC], g_kl [MM * CC];
__device__ __nv_bfloat16  g_vh [MM * CC], g_vl [MM * CC];
// transposed + split weights: Wt[N,K]
__device__ __nv_bfloat16  g_wah[3 * CC * CC],  g_wal[3 * CC * CC];   // w_attn^T
__device__ __nv_bfloat16  g_wph[CC * CC],      g_wpl[CC * CC];       // w_proj^T
__device__ __nv_bfloat16  g_wfh[4 * CC * CC],  g_wfl[4 * CC * CC];   // w_fc^T
__device__ __nv_bfloat16  g_w2h[CC * 4 * CC],  g_w2l[CC * 4 * CC];   // w_fc2^T

// ---------------------------------------------------------------------------
// Baseline-ISA helpers (sm_80+: cp.async, ldmatrix, mma.sync — NO tcgen05)
// ---------------------------------------------------------------------------
__device__ __forceinline__ uint32_t smem_u32(const void* p) {
    uint32_t a;
    asm("{ .reg .u64 t; cvta.to.shared.u64 t, %1; cvt.u32.u64 %0, t; }" : "=r"(a) : "l"(p));
    return a;
}

#define CP16(dst, src) \
    asm volatile("cp.async.cg.shared.global [%0], [%1], 16;" :: "r"(dst), "l"(src))
#define CP_COMMIT() asm volatile("cp.async.commit_group;")
#define CP_WAIT1()  asm volatile("cp.async.wait_group 1;")

__device__ __forceinline__ void ldsm_x4(uint32_t* r, uint32_t addr) {
    asm volatile("ldmatrix.sync.aligned.m8n8.x4.shared.b16 {%0,%1,%2,%3}, [%4];"
                 : "=r"(r[0]), "=r"(r[1]), "=r"(r[2]), "=r"(r[3]) : "r"(addr));
}
__device__ __forceinline__ void ldsm_x4_t(uint32_t* r, uint32_t addr) {
    asm volatile("ldmatrix.sync.aligned.m8n8.x4.trans.shared.b16 {%0,%1,%2,%3}, [%4];"
                 : "=r"(r[0]), "=r"(r[1]), "=r"(r[2]), "=r"(r[3]) : "r"(addr));
}

__device__ __forceinline__ void mma_bf16(float* d, const uint32_t* a, const uint32_t* b) {
    asm volatile(
        "mma.sync.aligned.m16n8k16.row.col.f32.bf16.bf16.f32 "
        "{%0,%1,%2,%3}, {%4,%5,%6,%7}, {%8,%9}, {%0,%1,%2,%3};"
        : "+f"(d[0]), "+f"(d[1]), "+f"(d[2]), "+f"(d[3])
        : "r"(a[0]), "r"(a[1]), "r"(a[2]), "r"(a[3]), "r"(b[0]), "r"(b[1]));
}

__device__ __forceinline__ void split2(float v, __nv_bfloat16& hi, __nv_bfloat16& lo) {
    hi = __float2bfloat16(v);
    lo = __float2bfloat16(v - __bfloat162float(hi));
}

// ---------------------------------------------------------------------------
// Weight transpose + split: W[K,N] fp32 -> Th[N,K], Tl[N,K] bf16
// ---------------------------------------------------------------------------
__global__ __launch_bounds__(256) void wsplit_t(
    const float* __restrict__ W, __nv_bfloat16* __restrict__ Th,
    __nv_bfloat16* __restrict__ Tl, int K, int N)
{
    __shared__ float t[32][33];
    const int tx = threadIdx.x, ty = threadIdx.y;
    const int n0 = blockIdx.x * 32, k0 = blockIdx.y * 32;
    #pragma unroll
    for (int i = 0; i < 4; i++)
        t[ty + i * 8][tx] = W[(size_t)(k0 + ty + i * 8) * N + n0 + tx];
    __syncthreads();
    #pragma unroll
    for (int i = 0; i < 4; i++) {
        float v = t[tx][ty + i * 8];
        __nv_bfloat16 hi, lo;
        split2(v, hi, lo);
        size_t idx = (size_t)(n0 + ty + i * 8) * K + k0 + tx;
        Th[idx] = hi;
        Tl[idx] = lo;
    }
}

// ---------------------------------------------------------------------------
// LayerNorm -> split bf16 hi/lo. One block per row, 256 threads, float4/thread.
// ---------------------------------------------------------------------------
__global__ __launch_bounds__(256) void ln_split(
    const float* __restrict__ x, const float* __restrict__ g,
    const float* __restrict__ b,
    __nv_bfloat16* __restrict__ oh, __nv_bfloat16* __restrict__ ol)
{
    __shared__ float red[8];
    __shared__ float s_mu, s_rstd;
    const int row = blockIdx.x;
    const int tid = threadIdx.x;
    const float4 v = ((const float4*)(x + (size_t)row * CC))[tid];

    float sum = v.x + v.y + v.z + v.w;
    #pragma unroll
    for (int o = 16; o; o >>= 1) sum += __shfl_xor_sync(0xffffffffu, sum, o);
    if ((tid & 31) == 0) red[tid >> 5] = sum;
    __syncthreads();
    if (tid < 8) {
        float t = red[tid];
        #pragma unroll
        for (int o = 4; o; o >>= 1) t += __shfl_xor_sync(0xffu, t, o);
        if (tid == 0) s_mu = t * (1.0f / CC);
    }
    __syncthreads();
    const float mu = s_mu;

    float dx = v.x - mu, dy = v.y - mu, dz = v.z - mu, dw = v.w - mu;
    float sq = dx * dx + dy * dy + dz * dz + dw * dw;
    #pragma unroll
    for (int o = 16; o; o >>= 1) sq += __shfl_xor_sync(0xffffffffu, sq, o);
    __syncthreads();
    if ((tid & 31) == 0) red[tid >> 5] = sq;
    __syncthreads();
    if (tid < 8) {
        float t = red[tid];
        #pragma unroll
        for (int o = 4; o; o >>= 1) t += __shfl_xor_sync(0xffu, t, o);
        if (tid == 0) s_rstd = rsqrtf(t * (1.0f / CC) + EPSV);
    }
    __syncthreads();
    const float rstd = s_rstd;

    const float4 gg = ((const float4*)g)[tid];
    const float4 bb = ((const float4*)b)[tid];
    float o0 = dx * rstd * gg.x + bb.x;
    float o1 = dy * rstd * gg.y + bb.y;
    float o2 = dz * rstd * gg.z + bb.z;
    float o3 = dw * rstd * gg.w + bb.w;

    __nv_bfloat162 h01, h23, l01, l23;
    split2(o0, h01.x, l01.x); split2(o1, h01.y, l01.y);
    split2(o2, h23.x, l23.x); split2(o3, h23.y, l23.y);
    size_t idx = (size_t)row * CC + tid * 4;
    *(__nv_bfloat162*)&oh[idx]     = h01;
    *(__nv_bfloat162*)&oh[idx + 2] = h23;
    *(__nv_bfloat162*)&ol[idx]     = l01;
    *(__nv_bfloat162*)&ol[idx + 2] = l23;
}

// ---------------------------------------------------------------------------
// Split-bf16 HMMA GEMM: C[M,N] = (Ah+Al)[M,K] @ (Bh+Bl)[N,K]^T (+epilogue)
// 128x128 CTA tile, BK=32, 3-stage cp.async pipeline, ONE barrier per chunk
// (top barrier of iter i orders reads of stage (i-1)%3 before its rewrite).
// ---------------------------------------------------------------------------
enum { EPI_F32 = 0, EPI_F32_RES = 1, EPI_GELU_BF16 = 2, EPI_QKV = 3 };

__device__ __forceinline__ float gelu_tanh(float x) {
    float x3 = x * x * x;
    float t = tanhf(0.7978845608028654f * (x + 0.044715f * x3));
    return 0.5f * x * (1.0f + t);
}

#define RS 80                     // smem row stride bytes (32 bf16 + 8 pad)
#define TILE_B (128 * RS)         // 10240 B per tile
#define STAGE_B (4 * TILE_B)      // Ah, Al, Bh, Bl
#define NSTAGE 3
#define GEMM_SMEM_BYTES (NSTAGE * STAGE_B)   // 122880

template <int EPI>
__global__ __launch_bounds__(256, 1) void gemm_tc(
    const __nv_bfloat16* __restrict__ Ah, const __nv_bfloat16* __restrict__ Al,
    const __nv_bfloat16* __restrict__ Bh, const __nv_bfloat16* __restrict__ Bl,
    const float* __restrict__ bias, const float* __restrict__ res,
    float* __restrict__ Cf, __nv_bfloat16* __restrict__ Chi,
    __nv_bfloat16* __restrict__ Clo,
    __nv_bfloat16* __restrict__ Qh, __nv_bfloat16* __restrict__ Ql,
    __nv_bfloat16* __restrict__ Kh, __nv_bfloat16* __restrict__ Kl,
    __nv_bfloat16* __restrict__ Vh, __nv_bfloat16* __restrict__ Vl,
    int M, int N, int K)
{
    extern __shared__ __align__(1024) char dsm[];
    const uint32_t smem = smem_u32(dsm);

    const int tid   = threadIdx.x;
    const int lane  = tid & 31;
    const int wid   = tid >> 5;
    const int warp_m = wid & 3;
    const int warp_n = wid >> 2;
    const int row0 = blockIdx.y * 128;
    const int col0 = blockIdx.x * 128;

    const int lrow = tid >> 1;
    const int seg0 = (tid & 1) * 2;
    const __nv_bfloat16* pAh = Ah + (size_t)(row0 + lrow) * K + seg0 * 8;
    const __nv_bfloat16* pAl = Al + (size_t)(row0 + lrow) * K + seg0 * 8;
    const __nv_bfloat16* pBh = Bh + (size_t)(col0 + lrow) * K + seg0 * 8;
    const __nv_bfloat16* pBl = Bl + (size_t)(col0 + lrow) * K + seg0 * 8;
    const uint32_t dbase = smem + lrow * RS + seg0 * 16;

    const int nk = K >> 5;     // BK=32 chunks

    auto load_stage = [&](int i) {
        const uint32_t d = dbase + (i % NSTAGE) * STAGE_B;
        const int k0 = i * 32;
        CP16(d,                       pAh + k0);
        CP16(d + 16,                  pAh + k0 + 8);
        CP16(d + TILE_B,              pAl + k0);
        CP16(d + TILE_B + 16,         pAl + k0 + 8);
        CP16(d + 2 * TILE_B,          pBh + k0);
        CP16(d + 2 * TILE_B + 16,     pBh + k0 + 8);
        CP16(d + 3 * TILE_B,          pBl + k0);
        CP16(d + 3 * TILE_B + 16,     pBl + k0 + 8);
    };

    float acc[2][8][4];
    #pragma unroll
    for (int i = 0; i < 2; i++)
        #pragma unroll
        for (int j = 0; j < 8; j++)
            #pragma unroll
            for (int q = 0; q < 4; q++) acc[i][j][q] = 0.0f;

    const uint32_t a_off = smem + (warp_m * 32 + (lane & 15)) * RS + ((lane >> 4) << 4);
    const uint32_t b_off = smem + 2 * TILE_B
                         + (warp_n * 64 + (lane & 7) + ((lane >> 4) & 1) * 8) * RS
                         + (((lane >> 3) & 1) << 4);

    load_stage(0); CP_COMMIT();
    load_stage(1); CP_COMMIT();

    for (int i = 0; i < nk; i++) {
        CP_WAIT1();
        __syncthreads();               // single barrier per chunk (NSTAGE=3)
        if (i + 2 < nk) load_stage(i + 2);
        CP_COMMIT();

        const uint32_t sb = (uint32_t)((i % NSTAGE) * STAGE_B);
        #pragma unroll
        for (int ks = 0; ks < 2; ks++) {
            uint32_t ah[2][4], al[2][4], bh[8][2], bl[8][2];
            #pragma unroll
            for (int mf = 0; mf < 2; mf++) {
                uint32_t ra = a_off + sb + mf * 16 * RS + ks * 32;
                ldsm_x4(ah[mf], ra);
                ldsm_x4(al[mf], ra + TILE_B);
            }
            #pragma unroll
            for (int p = 0; p < 4; p++) {
                uint32_t rb = b_off + sb + p * 16 * RS + ks * 32;
                uint32_t t[4];
                ldsm_x4(t, rb);
                bh[2 * p][0] = t[0]; bh[2 * p][1] = t[1];
                bh[2 * p + 1][0] = t[2]; bh[2 * p + 1][1] = t[3];
                ldsm_x4(t, rb + TILE_B);
                bl[2 * p][0] = t[0]; bl[2 * p][1] = t[1];
                bl[2 * p + 1][0] = t[2]; bl[2 * p + 1][1] = t[3];
            }
            #pragma unroll
            for (int mf = 0; mf < 2; mf++)
                #pragma unroll
                for (int j = 0; j < 8; j++) {
                    mma_bf16(acc[mf][j], ah[mf], bh[j]);
                    mma_bf16(acc[mf][j], ah[mf], bl[j]);
                    mma_bf16(acc[mf][j], al[mf], bh[j]);
                }
        }
    }

    // ---- epilogue ---------------------------------------------------------
    #pragma unroll
    for (int mf = 0; mf < 2; mf++) {
        const int rbase = row0 + warp_m * 32 + mf * 16 + (lane >> 2);
        #pragma unroll
        for (int h = 0; h < 2; h++) {
            const int r = rbase + h * 8;
            const size_t rowoff = (size_t)r * N;
            #pragma unroll
            for (int j = 0; j < 8; j++) {
                const int c = col0 + warp_n * 64 + j * 8 + (lane & 3) * 2;
                float o0 = acc[mf][j][h * 2 + 0] + bias[c + 0];
                float o1 = acc[mf][j][h * 2 + 1] + bias[c + 1];
                if (EPI == EPI_F32_RES) {
                    const float2 rv = *(const float2*)&res[rowoff + c];
                    o0 += rv.x; o1 += rv.y;
                    *(float2*)&Cf[rowoff + c] = make_float2(o0, o1);
                } else if (EPI == EPI_GELU_BF16) {
                    o0 = gelu_tanh(o0); o1 = gelu_tanh(o1);
                    __nv_bfloat162 hx, lx;
                    split2(o0, hx.x, lx.x); split2(o1, hx.y, lx.y);
                    *(__nv_bfloat162*)&Chi[rowoff + c] = hx;
                    *(__nv_bfloat162*)&Clo[rowoff + c] = lx;
                } else if (EPI == EPI_QKV) {
                    const int sec = c >> 10;            // 0=q 1=k 2=v
                    const int ci  = c & 1023;
                    const int hh_ = ci >> 6, d = ci & 63;
                    if (sec == 0) { o0 *= 0.125f; o1 *= 0.125f; }
                    const size_t idx =
                        ((size_t)((r >> 11) * NH + hh_) * TT + (r & 2047)) * HD + d;
                    __nv_bfloat162 hx, lx;
                    split2(o0, hx.x, lx.x); split2(o1, hx.y, lx.y);
                    __nv_bfloat16* dh = (sec == 0) ? Qh : (sec == 1) ? Kh : Vh;
                    __nv_bfloat16* dl = (sec == 0) ? Ql : (sec == 1) ? Kl : Vl;
                    *(__nv_bfloat162*)&dh[idx] = hx;
                    *(__nv_bfloat162*)&dl[idx] = lx;
                } else {
                    *(float2*)&Cf[rowoff + c] = make_float2(o0, o1);
                }
            }
        }
    }
}

// ---------------------------------------------------------------------------
// HMMA flash attention. QK^T: split-bf16 3-pass. PV: 2-pass (Ph·Vh + Pl·Vh —
// the Ph·Vl term is dropped and Vl is never loaded; error ~2^-9/sqrt(K) on
// the attention branch only). fp32 online softmax.
// Grid (T/128, B*NH), 256 threads = 8 warps x 16 q-rows.
// ---------------------------------------------------------------------------
#define AT_RS 144                      // 72 bf16 per row (conflict-free ldmatrix)
#define AT_Q_BYTES (128 * AT_RS)       // 18432 per tensor
#define AT_KV_T    (64 * AT_RS)        // 9216 per tensor
#define AT_STG     (3 * AT_KV_T)       // kh,kl,vh = 27648
#define AT_SMEM    (2 * AT_Q_BYTES + 2 * AT_STG)   // 92160

__global__ __launch_bounds__(256, 1) void attn_mma(
    const __nv_bfloat16* __restrict__ qh_g, const __nv_bfloat16* __restrict__ ql_g,
    const __nv_bfloat16* __restrict__ kh_g, const __nv_bfloat16* __restrict__ kl_g,
    const __nv_bfloat16* __restrict__ vh_g,
    __nv_bfloat16* __restrict__ yh, __nv_bfloat16* __restrict__ yl)
{
    extern __shared__ __align__(1024) char sm[];
    const uint32_t smem = smem_u32(sm);
    const int qt = blockIdx.x;
    const int bh = blockIdx.y;
    const int b = bh >> 4, h = bh & 15;
    const int tid = threadIdx.x, lane = tid & 31, w = tid >> 5;

    const uint32_t SQH = smem, SQL = smem + AT_Q_BYTES, SKV = smem + 2 * AT_Q_BYTES;
    const size_t gbase = (size_t)bh * TT * HD;

    auto load_kv = [&](int kt, int s) {
        const uint32_t dst0 = SKV + s * AT_STG;
        #pragma unroll
        for (int rep = 0; rep < 2; rep++) {
            int ch = rep * 256 + tid;          // 0..511
            int row = ch >> 3, c = ch & 7;
            size_t go = gbase + (size_t)(kt * 64 + row) * HD + c * 8;
            uint32_t d = dst0 + row * AT_RS + c * 16;
            CP16(d,               kh_g + go);
            CP16(d + AT_KV_T,     kl_g + go);
            CP16(d + 2 * AT_KV_T, vh_g + go);
        }
    };

    // prologue: Q (both) + KV tile 0 in group 0
    {
        #pragma unroll
        for (int rep = 0; rep < 4; rep++) {
            int ch = rep * 256 + tid;          // 0..1023
            int row = ch >> 3, c = ch & 7;
            size_t go = gbase + (size_t)(qt * 128 + row) * HD + c * 8;
            CP16(SQH + row * AT_RS + c * 16, qh_g + go);
            CP16(SQL + row * AT_RS + c * 16, ql_g + go);
        }
        load_kv(0, 0);
        CP_COMMIT();
    }

    float O[8][4];
    #pragma unroll
    for (int j = 0; j < 8; j++)
        #pragma unroll
        for (int q = 0; q < 4; q++) O[j][q] = 0.0f;
    float m0 = -1e30f, m1 = -1e30f, l0 = 0.0f, l1 = 0.0f;
    uint32_t qfh[4][4], qfl[4][4];

    const int ktmax = 2 * qt + 1;
    const int r0g = qt * 128 + w * 16 + (lane >> 2);

    for (int kt = 0; kt <= ktmax; kt++) {
        if (kt + 1 <= ktmax) load_kv(kt + 1, (kt + 1) & 1);
        CP_COMMIT();
        CP_WAIT1();
        __syncthreads();

        if (kt == 0) {
            const uint32_t aq = (w * 16 + (lane & 15)) * AT_RS + ((lane >> 4) << 4);
            #pragma unroll
            for (int kk = 0; kk < 4; kk++) {
                ldsm_x4(qfh[kk], SQH + aq + kk * 32);
                ldsm_x4(qfl[kk], SQL + aq + kk * 32);
            }
        }

        const uint32_t kh_s = SKV + (kt & 1) * AT_STG;
        const uint32_t kl_s = kh_s + AT_KV_T;
        const uint32_t vh_s = kh_s + 2 * AT_KV_T;

        // ---- S = Q K^T (3-pass) ------------------------------------------
        float S[8][4];
        #pragma unroll
        for (int j = 0; j < 8; j++)
            #pragma unroll
            for (int q = 0; q < 4; q++) S[j][q] = 0.0f;

        const uint32_t brow = ((lane & 7) + ((lane >> 4) & 1) * 8) * AT_RS
                            + (((lane >> 3) & 1) << 4);
        #pragma unroll
        for (int kk = 0; kk < 4; kk++) {
            uint32_t bhf[8][2], blf[8][2];
            #pragma unroll
            for (int p = 0; p < 4; p++) {
                uint32_t t4[4];
                uint32_t ad = brow + p * 16 * AT_RS + kk * 32;
                ldsm_x4(t4, kh_s + ad);
                bhf[2 * p][0] = t4[0]; bhf[2 * p][1] = t4[1];
                bhf[2 * p + 1][0] = t4[2]; bhf[2 * p + 1][1] = t4[3];
                ldsm_x4(t4, kl_s + ad);
                blf[2 * p][0] = t4[0]; blf[2 * p][1] = t4[1];
                blf[2 * p + 1][0] = t4[2]; blf[2 * p + 1][1] = t4[3];
            }
            #pragma unroll
            for (int j = 0; j < 8; j++) {
                mma_bf16(S[j], qfh[kk], bhf[j]);
                mma_bf16(S[j], qfh[kk], blf[j]);
                mma_bf16(S[j], qfl[kk], bhf[j]);
            }
        }

        // ---- causal mask (only tiles kt >= 2*qt can cross the diagonal) --
        if (kt >= 2 * qt) {
            #pragma unroll
            for (int j = 0; j < 8; j++) {
                int key = kt * 64 + j * 8 + (lane & 3) * 2;
                if (key     > r0g)     S[j][0] = -1e30f;
                if (key + 1 > r0g)     S[j][1] = -1e30f;
                if (key     > r0g + 8) S[j][2] = -1e30f;
                if (key + 1 > r0g + 8) S[j][3] = -1e30f;
            }
        }

        // ---- online softmax ----------------------------------------------
        float mx0 = -1e30f, mx1 = -1e30f;
        #pragma unroll
        for (int j = 0; j < 8; j++) {
            mx0 = fmaxf(mx0, fmaxf(S[j][0], S[j][1]));
            mx1 = fmaxf(mx1, fmaxf(S[j][2], S[j][3]));
        }
        mx0 = fmaxf(mx0, __shfl_xor_sync(0xffffffffu, mx0, 1));
        mx0 = fmaxf(mx0, __shfl_xor_sync(0xffffffffu, mx0, 2));
        mx1 = fmaxf(mx1, __shfl_xor_sync(0xffffffffu, mx1, 1));
        mx1 = fmaxf(mx1, __shfl_xor_sync(0xffffffffu, mx1, 2));
        float mn0 = fmaxf(m0, mx0), mn1 = fmaxf(m1, mx1);
        float sc0 = __expf(m0 - mn0), sc1 = __expf(m1 - mn1);
        m0 = mn0; m1 = mn1;
        l0 *= sc0; l1 *= sc1;
        #pragma unroll
        for (int j = 0; j < 8; j++) {
            O[j][0] *= sc0; O[j][1] *= sc0; O[j][2] *= sc1; O[j][3] *= sc1;
            S[j][0] = __expf(S[j][0] - mn0);
            S[j][1] = __expf(S[j][1] - mn0);
            S[j][2] = __expf(S[j][2] - mn1);
            S[j][3] = __expf(S[j][3] - mn1);
            l0 += S[j][0] + S[j][1];
            l1 += S[j][2] + S[j][3];
        }

        // ---- O += P V (2-pass: Ph·Vh + Pl·Vh) ----------------------------
        #pragma unroll
        for (int kk = 0; kk < 4; kk++) {
            uint32_t ph[4], pl[4];
            #pragma unroll
            for (int u = 0; u < 2; u++) {
                int j = 2 * kk + u;
                __nv_bfloat162 hA, lA, hB, lB;
                split2(S[j][0], hA.x, lA.x); split2(S[j][1], hA.y, lA.y);
                split2(S[j][2], hB.x, lB.x); split2(S[j][3], hB.y, lB.y);
                ph[0 + u * 2] = *(uint32_t*)&hA;
                ph[1 + u * 2] = *(uint32_t*)&hB;
                pl[0 + u * 2] = *(uint32_t*)&lA;
                pl[1 + u * 2] = *(uint32_t*)&lB;
            }
            const uint32_t vrow = (kk * 16 + (lane & 15)) * AT_RS + ((lane >> 4) << 4);
            #pragma unroll
            for (int dp = 0; dp < 4; dp++) {
                uint32_t t4[4];
                uint32_t ad = vrow + dp * 32;
                ldsm_x4_t(t4, vh_s + ad);
                mma_bf16(O[2 * dp],     ph, t4);
                mma_bf16(O[2 * dp + 1], ph, t4 + 2);
                mma_bf16(O[2 * dp],     pl, t4);
                mma_bf16(O[2 * dp + 1], pl, t4 + 2);
            }
        }
        __syncthreads();
    }

    // ---- finalize + write y split bf16 -----------------------------------
    l0 += __shfl_xor_sync(0xffffffffu, l0, 1);
    l0 += __shfl_xor_sync(0xffffffffu, l0, 2);
    l1 += __shfl_xor_sync(0xffffffffu, l1, 1);
    l1 += __shfl_xor_sync(0xffffffffu, l1, 2);
    const float inv0 = 1.0f / l0, inv1 = 1.0f / l1;

    const size_t yb0 = (size_t)(b * TT + qt * 128 + w * 16 + (lane >> 2)) * CC + h * HD;
    const size_t yb1 = yb0 + (size_t)8 * CC;
    #pragma unroll
    for (int j = 0; j < 8; j++) {
        const int d = j * 8 + (lane & 3) * 2;
        __nv_bfloat162 hx, lx;
        split2(O[j][0] * inv0, hx.x, lx.x);
        split2(O[j][1] * inv0, hx.y, lx.y);
        *(__nv_bfloat162*)&yh[yb0 + d] = hx;
        *(__nv_bfloat162*)&yl[yb0 + d] = lx;
        split2(O[j][2] * inv1, hx.x, lx.x);
        split2(O[j][3] * inv1, hx.y, lx.y);
        *(__nv_bfloat162*)&yh[yb1 + d] = hx;
        *(__nv_bfloat162*)&yl[yb1 + d] = lx;
    }
}

// ---------------------------------------------------------------------------
extern "C" void kernel_launch(void* const* d_in, const int* in_sizes, int n_in,
                              void* d_out, int out_size)
{
    const float* x      = (const float*)d_in[0];
    const float* ln1_g  = (const float*)d_in[1];
    const float* ln1_b  = (const float*)d_in[2];
    const float* w_attn = (const float*)d_in[3];
    const float* b_attn = (const float*)d_in[4];
    const float* w_proj = (const float*)d_in[5];
    const float* b_proj = (const float*)d_in[6];
    const float* ln2_g  = (const float*)d_in[7];
    const float* ln2_b  = (const float*)d_in[8];
    const float* w_fc   = (const float*)d_in[9];
    const float* b_fc   = (const float*)d_in[10];
    const float* w_fc2  = (const float*)d_in[11];
    const float* b_fc2  = (const float*)d_in[12];
    float* out = (float*)d_out;

    float *x1p;
    __nv_bfloat16 *lnh, *lnl, *yh, *yl, *hh, *hl;
    __nv_bfloat16 *qh, *ql, *kh, *kl, *vh, *vl;
    __nv_bfloat16 *wah, *wal, *wph, *wpl, *wfh, *wfl, *w2h, *w2l;
    cudaGetSymbolAddress((void**)&x1p,  g_x1);
    cudaGetSymbolAddress((void**)&lnh,  g_lnh);  cudaGetSymbolAddress((void**)&lnl, g_lnl);
    cudaGetSymbolAddress((void**)&yh,   g_yh);   cudaGetSymbolAddress((void**)&yl,  g_yl);
    cudaGetSymbolAddress((void**)&hh,   g_hh);   cudaGetSymbolAddress((void**)&hl,  g_hl);
    cudaGetSymbolAddress((void**)&qh,   g_qh);   cudaGetSymbolAddress((void**)&ql,  g_ql);
    cudaGetSymbolAddress((void**)&kh,   g_kh);   cudaGetSymbolAddress((void**)&kl,  g_kl);
    cudaGetSymbolAddress((void**)&vh,   g_vh);   cudaGetSymbolAddress((void**)&vl,  g_vl);
    cudaGetSymbolAddress((void**)&wah,  g_wah);  cudaGetSymbolAddress((void**)&wal, g_wal);
    cudaGetSymbolAddress((void**)&wph,  g_wph);  cudaGetSymbolAddress((void**)&wpl, g_wpl);
    cudaGetSymbolAddress((void**)&wfh,  g_wfh);  cudaGetSymbolAddress((void**)&wfl, g_wfl);
    cudaGetSymbolAddress((void**)&w2h,  g_w2h);  cudaGetSymbolAddress((void**)&w2l, g_w2l);

    cudaFuncSetAttribute(gemm_tc<EPI_QKV>,       cudaFuncAttributeMaxDynamicSharedMemorySize, GEMM_SMEM_BYTES);
    cudaFuncSetAttribute(gemm_tc<EPI_F32_RES>,   cudaFuncAttributeMaxDynamicSharedMemorySize, GEMM_SMEM_BYTES);
    cudaFuncSetAttribute(gemm_tc<EPI_GELU_BF16>, cudaFuncAttributeMaxDynamicSharedMemorySize, GEMM_SMEM_BYTES);
    cudaFuncSetAttribute(attn_mma, cudaFuncAttributeMaxDynamicSharedMemorySize, AT_SMEM);

    const dim3 tb(32, 8);
    wsplit_t<<<dim3(3 * CC / 32, CC / 32), tb>>>(w_attn, wah, wal, CC, 3 * CC);
    wsplit_t<<<dim3(CC / 32, CC / 32), tb>>>(w_proj, wph, wpl, CC, CC);
    wsplit_t<<<dim3(4 * CC / 32, CC / 32), tb>>>(w_fc, wfh, wfl, CC, 4 * CC);
    wsplit_t<<<dim3(CC / 32, 4 * CC / 32), tb>>>(w_fc2, w2h, w2l, 4 * CC, CC);

    // 1) LN1
    ln_split<<<MM, 256>>>(x, ln1_g, ln1_b, lnh, lnl);
    // 2) qkv GEMM -> split q(scaled)/k/v bf16 in [bh][t][d]
    gemm_tc<EPI_QKV><<<dim3(3 * CC / 128, MM / 128), 256, GEMM_SMEM_BYTES>>>(
        lnh, lnl, wah, wal, b_attn, nullptr, nullptr, nullptr, nullptr,
        qh, ql, kh, kl, vh, vl, MM, 3 * CC, CC);
    // 3) HMMA flash attention -> y split
    attn_mma<<<dim3(TT / 128, BB * NH), 256, AT_SMEM>>>(qh, ql, kh, kl, vh, yh, yl);
    // 4) x1 = x + y @ w_proj + b_proj
    gemm_tc<EPI_F32_RES><<<dim3(CC / 128, MM / 128), 256, GEMM_SMEM_BYTES>>>(
        yh, yl, wph, wpl, b_proj, x, x1p, nullptr, nullptr,
        nullptr, nullptr, nullptr, nullptr, nullptr, nullptr, MM, CC, CC);
    // 5) LN2
    ln_split<<<MM, 256>>>(x1p, ln2_g, ln2_b, lnh, lnl);
    // 6) hfc = gelu(ln @ w_fc + b_fc) -> split bf16
    gemm_tc<EPI_GELU_BF16><<<dim3(4 * CC / 128, MM / 128), 256, GEMM_SMEM_BYTES>>>(
        lnh, lnl, wfh, wfl, b_fc, nullptr, nullptr, hh, hl,
        nullptr, nullptr, nullptr, nullptr, nullptr, nullptr, MM, 4 * CC, CC);
    // 7) out = x1 + hfc @ w_fc2 + b_fc2
    gemm_tc<EPI_F32_RES><<<dim3(CC / 128, MM / 128), 256, GEMM_SMEM_BYTES>>>(
        hh, hl, w2h, w2l, b_fc2, x1p, out, nullptr, nullptr,
        nullptr, nullptr, nullptr, nullptr, nullptr, nullptr, MM, CC, 4 * CC);
}

// round 17
// speedup vs baseline: 1.9166x; 1.1026x over previous
#include <cuda_runtime.h>
#include <cuda_bf16.h>
#include <cstdint>
#include <math.h>

// Problem constants
#define BB 4
#define TT 2048
#define CC 1024
#define NH 16
#define HD 64
#define MM (BB * TT)          // 8192 tokens
#define EPSV 1e-5f

// -------------------- scratch (static device globals; no allocation) --------
__device__ float          g_x1 [MM * CC];         // residual after attention (fp32)
__device__ __nv_bfloat16  g_lnh[MM * CC],      g_lnl[MM * CC];       // LN out split
__device__ __nv_bfloat16  g_yh [MM * CC],      g_yl [MM * CC];       // attn out split
__device__ __nv_bfloat16  g_hh [MM * 4 * CC],  g_hl [MM * 4 * CC];   // gelu(fc) split
// q/k/v split bf16, layout [bh][t][d]  (bh = b*16+h)
__device__ __nv_bfloat16  g_qh [MM * CC], g_ql [MM * CC];
__device__ __nv_bfloat16  g_kh [MM * CC], g_kl [MM * CC];
__device__ __nv_bfloat16  g_vh [MM * CC], g_vl [MM * CC];
// transposed + split weights: Wt[N,K]
__device__ __nv_bfloat16  g_wah[3 * CC * CC],  g_wal[3 * CC * CC];   // w_attn^T
__device__ __nv_bfloat16  g_wph[CC * CC],      g_wpl[CC * CC];       // w_proj^T
__device__ __nv_bfloat16  g_wfh[4 * CC * CC],  g_wfl[4 * CC * CC];   // w_fc^T
__device__ __nv_bfloat16  g_w2h[CC * 4 * CC],  g_w2l[CC * 4 * CC];   // w_fc2^T

// ---------------------------------------------------------------------------
// Baseline-ISA helpers (sm_80+: cp.async, ldmatrix, mma.sync — NO tcgen05)
// ---------------------------------------------------------------------------
__device__ __forceinline__ uint32_t smem_u32(const void* p) {
    uint32_t a;
    asm("{ .reg .u64 t; cvta.to.shared.u64 t, %1; cvt.u32.u64 %0, t; }" : "=r"(a) : "l"(p));
    return a;
}

#define CP16(dst, src) \
    asm volatile("cp.async.cg.shared.global [%0], [%1], 16;" :: "r"(dst), "l"(src))
#define CP_COMMIT() asm volatile("cp.async.commit_group;")
#define CP_WAIT1()  asm volatile("cp.async.wait_group 1;")

__device__ __forceinline__ void ldsm_x4(uint32_t* r, uint32_t addr) {
    asm volatile("ldmatrix.sync.aligned.m8n8.x4.shared.b16 {%0,%1,%2,%3}, [%4];"
                 : "=r"(r[0]), "=r"(r[1]), "=r"(r[2]), "=r"(r[3]) : "r"(addr));
}
__device__ __forceinline__ void ldsm_x4_t(uint32_t* r, uint32_t addr) {
    asm volatile("ldmatrix.sync.aligned.m8n8.x4.trans.shared.b16 {%0,%1,%2,%3}, [%4];"
                 : "=r"(r[0]), "=r"(r[1]), "=r"(r[2]), "=r"(r[3]) : "r"(addr));
}

__device__ __forceinline__ void mma_bf16(float* d, const uint32_t* a, const uint32_t* b) {
    asm volatile(
        "mma.sync.aligned.m16n8k16.row.col.f32.bf16.bf16.f32 "
        "{%0,%1,%2,%3}, {%4,%5,%6,%7}, {%8,%9}, {%0,%1,%2,%3};"
        : "+f"(d[0]), "+f"(d[1]), "+f"(d[2]), "+f"(d[3])
        : "r"(a[0]), "r"(a[1]), "r"(a[2]), "r"(a[3]), "r"(b[0]), "r"(b[1]));
}

__device__ __forceinline__ void split2(float v, __nv_bfloat16& hi, __nv_bfloat16& lo) {
    hi = __float2bfloat16(v);
    lo = __float2bfloat16(v - __bfloat162float(hi));
}

// ---------------------------------------------------------------------------
// Weight transpose + split: W[K,N] fp32 -> Th[N,K], Tl[N,K] bf16
// ---------------------------------------------------------------------------
__global__ __launch_bounds__(256) void wsplit_t(
    const float* __restrict__ W, __nv_bfloat16* __restrict__ Th,
    __nv_bfloat16* __restrict__ Tl, int K, int N)
{
    __shared__ float t[32][33];
    const int tx = threadIdx.x, ty = threadIdx.y;
    const int n0 = blockIdx.x * 32, k0 = blockIdx.y * 32;
    #pragma unroll
    for (int i = 0; i < 4; i++)
        t[ty + i * 8][tx] = W[(size_t)(k0 + ty + i * 8) * N + n0 + tx];
    __syncthreads();
    #pragma unroll
    for (int i = 0; i < 4; i++) {
        float v = t[tx][ty + i * 8];
        __nv_bfloat16 hi, lo;
        split2(v, hi, lo);
        size_t idx = (size_t)(n0 + ty + i * 8) * K + k0 + tx;
        Th[idx] = hi;
        Tl[idx] = lo;
    }
}

// ---------------------------------------------------------------------------
// LayerNorm -> split bf16 hi/lo. One block per row, 256 threads, float4/thread.
// ---------------------------------------------------------------------------
__global__ __launch_bounds__(256) void ln_split(
    const float* __restrict__ x, const float* __restrict__ g,
    const float* __restrict__ b,
    __nv_bfloat16* __restrict__ oh, __nv_bfloat16* __restrict__ ol)
{
    __shared__ float red[8];
    __shared__ float s_mu, s_rstd;
    const int row = blockIdx.x;
    const int tid = threadIdx.x;
    const float4 v = ((const float4*)(x + (size_t)row * CC))[tid];

    float sum = v.x + v.y + v.z + v.w;
    #pragma unroll
    for (int o = 16; o; o >>= 1) sum += __shfl_xor_sync(0xffffffffu, sum, o);
    if ((tid & 31) == 0) red[tid >> 5] = sum;
    __syncthreads();
    if (tid < 8) {
        float t = red[tid];
        #pragma unroll
        for (int o = 4; o; o >>= 1) t += __shfl_xor_sync(0xffu, t, o);
        if (tid == 0) s_mu = t * (1.0f / CC);
    }
    __syncthreads();
    const float mu = s_mu;

    float dx = v.x - mu, dy = v.y - mu, dz = v.z - mu, dw = v.w - mu;
    float sq = dx * dx + dy * dy + dz * dz + dw * dw;
    #pragma unroll
    for (int o = 16; o; o >>= 1) sq += __shfl_xor_sync(0xffffffffu, sq, o);
    __syncthreads();
    if ((tid & 31) == 0) red[tid >> 5] = sq;
    __syncthreads();
    if (tid < 8) {
        float t = red[tid];
        #pragma unroll
        for (int o = 4; o; o >>= 1) t += __shfl_xor_sync(0xffu, t, o);
        if (tid == 0) s_rstd = rsqrtf(t * (1.0f / CC) + EPSV);
    }
    __syncthreads();
    const float rstd = s_rstd;

    const float4 gg = ((const float4*)g)[tid];
    const float4 bb = ((const float4*)b)[tid];
    float o0 = dx * rstd * gg.x + bb.x;
    float o1 = dy * rstd * gg.y + bb.y;
    float o2 = dz * rstd * gg.z + bb.z;
    float o3 = dw * rstd * gg.w + bb.w;

    __nv_bfloat162 h01, h23, l01, l23;
    split2(o0, h01.x, l01.x); split2(o1, h01.y, l01.y);
    split2(o2, h23.x, l23.x); split2(o3, h23.y, l23.y);
    size_t idx = (size_t)row * CC + tid * 4;
    *(__nv_bfloat162*)&oh[idx]     = h01;
    *(__nv_bfloat162*)&oh[idx + 2] = h23;
    *(__nv_bfloat162*)&ol[idx]     = l01;
    *(__nv_bfloat162*)&ol[idx + 2] = l23;
}

// ---------------------------------------------------------------------------
// Split-bf16 HMMA GEMM: C[M,N] = (Ah+Al)[M,K] @ (Bh+Bl)[N,K]^T (+epilogue)
// 128x128 CTA tile, BK=32, 2-stage cp.async pipeline, 2 CTAs/SM.
// Pass-major MMA ordering: each pass issues 16 MMAs into distinct
// accumulators (no RAW chains); B fragments loaded once per hh+lh, once for hl.
// ---------------------------------------------------------------------------
enum { EPI_F32 = 0, EPI_F32_RES = 1, EPI_GELU_BF16 = 2, EPI_QKV = 3 };

__device__ __forceinline__ float gelu_tanh(float x) {
    float x3 = x * x * x;
    float t = tanhf(0.7978845608028654f * (x + 0.044715f * x3));
    return 0.5f * x * (1.0f + t);
}

#define RS 80                     // smem row stride bytes (32 bf16 + 8 pad)
#define TILE_B (128 * RS)         // 10240 B per tile
#define STAGE_B (4 * TILE_B)      // Ah, Al, Bh, Bl = 40960
#define NSTAGE 2
#define GEMM_SMEM_BYTES (NSTAGE * STAGE_B)   // 81920 -> 2 CTAs/SM

template <int EPI>
__global__ __launch_bounds__(256, 2) void gemm_tc(
    const __nv_bfloat16* __restrict__ Ah, const __nv_bfloat16* __restrict__ Al,
    const __nv_bfloat16* __restrict__ Bh, const __nv_bfloat16* __restrict__ Bl,
    const float* __restrict__ bias, const float* __restrict__ res,
    float* __restrict__ Cf, __nv_bfloat16* __restrict__ Chi,
    __nv_bfloat16* __restrict__ Clo,
    __nv_bfloat16* __restrict__ Qh, __nv_bfloat16* __restrict__ Ql,
    __nv_bfloat16* __restrict__ Kh, __nv_bfloat16* __restrict__ Kl,
    __nv_bfloat16* __restrict__ Vh, __nv_bfloat16* __restrict__ Vl,
    int M, int N, int K)
{
    extern __shared__ __align__(1024) char dsm[];
    const uint32_t smem = smem_u32(dsm);

    const int tid   = threadIdx.x;
    const int lane  = tid & 31;
    const int wid   = tid >> 5;
    const int warp_m = wid & 3;
    const int warp_n = wid >> 2;
    const int row0 = blockIdx.y * 128;
    const int col0 = blockIdx.x * 128;

    const int lrow = tid >> 1;
    const int seg0 = (tid & 1) * 2;
    const __nv_bfloat16* pAh = Ah + (size_t)(row0 + lrow) * K + seg0 * 8;
    const __nv_bfloat16* pAl = Al + (size_t)(row0 + lrow) * K + seg0 * 8;
    const __nv_bfloat16* pBh = Bh + (size_t)(col0 + lrow) * K + seg0 * 8;
    const __nv_bfloat16* pBl = Bl + (size_t)(col0 + lrow) * K + seg0 * 8;
    const uint32_t dbase = smem + lrow * RS + seg0 * 16;

    const int nk = K >> 5;     // BK=32 chunks

    auto load_stage = [&](int i) {
        const uint32_t d = dbase + (i & 1) * STAGE_B;
        const int k0 = i * 32;
        CP16(d,                       pAh + k0);
        CP16(d + 16,                  pAh + k0 + 8);
        CP16(d + TILE_B,              pAl + k0);
        CP16(d + TILE_B + 16,         pAl + k0 + 8);
        CP16(d + 2 * TILE_B,          pBh + k0);
        CP16(d + 2 * TILE_B + 16,     pBh + k0 + 8);
        CP16(d + 3 * TILE_B,          pBl + k0);
        CP16(d + 3 * TILE_B + 16,     pBl + k0 + 8);
    };

    float acc[2][8][4];
    #pragma unroll
    for (int i = 0; i < 2; i++)
        #pragma unroll
        for (int j = 0; j < 8; j++)
            #pragma unroll
            for (int q = 0; q < 4; q++) acc[i][j][q] = 0.0f;

    const uint32_t a_off = smem + (warp_m * 32 + (lane & 15)) * RS + ((lane >> 4) << 4);
    const uint32_t b_off = smem + 2 * TILE_B
                         + (warp_n * 64 + (lane & 7) + ((lane >> 4) & 1) * 8) * RS
                         + (((lane >> 3) & 1) << 4);

    load_stage(0); CP_COMMIT();

    for (int i = 0; i < nk; i++) {
        if (i + 1 < nk) load_stage(i + 1);   // writes buffer (i+1)&1; prev compute
        CP_COMMIT();                         //   of that buffer ended at bottom sync
        CP_WAIT1();                          // stage i complete
        __syncthreads();

        const uint32_t sb = (uint32_t)((i & 1) * STAGE_B);
        #pragma unroll
        for (int ks = 0; ks < 2; ks++) {
            uint32_t af[4][4];               // [0..1]=Ah mf frags, [2..3]=Al
            #pragma unroll
            for (int mf = 0; mf < 2; mf++) {
                uint32_t ra = a_off + sb + mf * 16 * RS + ks * 32;
                ldsm_x4(af[mf], ra);
                ldsm_x4(af[2 + mf], ra + TILE_B);
            }
            uint32_t bf[8][2];
            #pragma unroll
            for (int p = 0; p < 4; p++) {    // Bh fragments
                uint32_t t4[4];
                ldsm_x4(t4, b_off + sb + p * 16 * RS + ks * 32);
                bf[2 * p][0] = t4[0]; bf[2 * p][1] = t4[1];
                bf[2 * p + 1][0] = t4[2]; bf[2 * p + 1][1] = t4[3];
            }
            // pass 1: Ah x Bh  (16 independent accumulators)
            #pragma unroll
            for (int mf = 0; mf < 2; mf++)
                #pragma unroll
                for (int j = 0; j < 8; j++)
                    mma_bf16(acc[mf][j], af[mf], bf[j]);
            // pass 2: Al x Bh  (Bh still resident)
            #pragma unroll
            for (int mf = 0; mf < 2; mf++)
                #pragma unroll
                for (int j = 0; j < 8; j++)
                    mma_bf16(acc[mf][j], af[2 + mf], bf[j]);
            // reload B with Bl, pass 3: Ah x Bl
            #pragma unroll
            for (int p = 0; p < 4; p++) {
                uint32_t t4[4];
                ldsm_x4(t4, b_off + sb + TILE_B + p * 16 * RS + ks * 32);
                bf[2 * p][0] = t4[0]; bf[2 * p][1] = t4[1];
                bf[2 * p + 1][0] = t4[2]; bf[2 * p + 1][1] = t4[3];
            }
            #pragma unroll
            for (int mf = 0; mf < 2; mf++)
                #pragma unroll
                for (int j = 0; j < 8; j++)
                    mma_bf16(acc[mf][j], af[mf], bf[j]);
        }
        __syncthreads();                     // reads of stage i done before its rewrite
    }

    // ---- epilogue ---------------------------------------------------------
    #pragma unroll
    for (int mf = 0; mf < 2; mf++) {
        const int rbase = row0 + warp_m * 32 + mf * 16 + (lane >> 2);
        #pragma unroll
        for (int h = 0; h < 2; h++) {
            const int r = rbase + h * 8;
            const size_t rowoff = (size_t)r * N;
            #pragma unroll
            for (int j = 0; j < 8; j++) {
                const int c = col0 + warp_n * 64 + j * 8 + (lane & 3) * 2;
                float o0 = acc[mf][j][h * 2 + 0] + bias[c + 0];
                float o1 = acc[mf][j][h * 2 + 1] + bias[c + 1];
                if (EPI == EPI_F32_RES) {
                    const float2 rv = *(const float2*)&res[rowoff + c];
                    o0 += rv.x; o1 += rv.y;
                    *(float2*)&Cf[rowoff + c] = make_float2(o0, o1);
                } else if (EPI == EPI_GELU_BF16) {
                    o0 = gelu_tanh(o0); o1 = gelu_tanh(o1);
                    __nv_bfloat162 hx, lx;
                    split2(o0, hx.x, lx.x); split2(o1, hx.y, lx.y);
                    *(__nv_bfloat162*)&Chi[rowoff + c] = hx;
                    *(__nv_bfloat162*)&Clo[rowoff + c] = lx;
                } else if (EPI == EPI_QKV) {
                    const int sec = c >> 10;            // 0=q 1=k 2=v
                    const int ci  = c & 1023;
                    const int hh_ = ci >> 6, d = ci & 63;
                    if (sec == 0) { o0 *= 0.125f; o1 *= 0.125f; }
                    const size_t idx =
                        ((size_t)((r >> 11) * NH + hh_) * TT + (r & 2047)) * HD + d;
                    __nv_bfloat162 hx, lx;
                    split2(o0, hx.x, lx.x); split2(o1, hx.y, lx.y);
                    __nv_bfloat16* dh = (sec == 0) ? Qh : (sec == 1) ? Kh : Vh;
                    __nv_bfloat16* dl = (sec == 0) ? Ql : (sec == 1) ? Kl : Vl;
                    *(__nv_bfloat162*)&dh[idx] = hx;
                    *(__nv_bfloat162*)&dl[idx] = lx;
                } else {
                    *(float2*)&Cf[rowoff + c] = make_float2(o0, o1);
                }
            }
        }
    }
}

// ---------------------------------------------------------------------------
// HMMA flash attention. QK^T: split-bf16 3-pass. PV: 2-pass (Ph·Vh + Pl·Vh).
// fp32 online softmax. Grid (T/128, B*NH), 256 threads = 8 warps x 16 q-rows.
// ---------------------------------------------------------------------------
#define AT_RS 144                      // 72 bf16 per row (conflict-free ldmatrix)
#define AT_Q_BYTES (128 * AT_RS)       // 18432 per tensor
#define AT_KV_T    (64 * AT_RS)        // 9216 per tensor
#define AT_STG     (3 * AT_KV_T)       // kh,kl,vh = 27648
#define AT_SMEM    (2 * AT_Q_BYTES + 2 * AT_STG)   // 92160

__global__ __launch_bounds__(256, 1) void attn_mma(
    const __nv_bfloat16* __restrict__ qh_g, const __nv_bfloat16* __restrict__ ql_g,
    const __nv_bfloat16* __restrict__ kh_g, const __nv_bfloat16* __restrict__ kl_g,
    const __nv_bfloat16* __restrict__ vh_g,
    __nv_bfloat16* __restrict__ yh, __nv_bfloat16* __restrict__ yl)
{
    extern __shared__ __align__(1024) char sm[];
    const uint32_t smem = smem_u32(sm);
    const int qt = blockIdx.x;
    const int bh = blockIdx.y;
    const int b = bh >> 4, h = bh & 15;
    const int tid = threadIdx.x, lane = tid & 31, w = tid >> 5;

    const uint32_t SQH = smem, SQL = smem + AT_Q_BYTES, SKV = smem + 2 * AT_Q_BYTES;
    const size_t gbase = (size_t)bh * TT * HD;

    auto load_kv = [&](int kt, int s) {
        const uint32_t dst0 = SKV + s * AT_STG;
        #pragma unroll
        for (int rep = 0; rep < 2; rep++) {
            int ch = rep * 256 + tid;          // 0..511
            int row = ch >> 3, c = ch & 7;
            size_t go = gbase + (size_t)(kt * 64 + row) * HD + c * 8;
            uint32_t d = dst0 + row * AT_RS + c * 16;
            CP16(d,               kh_g + go);
            CP16(d + AT_KV_T,     kl_g + go);
            CP16(d + 2 * AT_KV_T, vh_g + go);
        }
    };

    // prologue: Q (both) + KV tile 0 in group 0
    {
        #pragma unroll
        for (int rep = 0; rep < 4; rep++) {
            int ch = rep * 256 + tid;          // 0..1023
            int row = ch >> 3, c = ch & 7;
            size_t go = gbase + (size_t)(qt * 128 + row) * HD + c * 8;
            CP16(SQH + row * AT_RS + c * 16, qh_g + go);
            CP16(SQL + row * AT_RS + c * 16, ql_g + go);
        }
        load_kv(0, 0);
        CP_COMMIT();
    }

    float O[8][4];
    #pragma unroll
    for (int j = 0; j < 8; j++)
        #pragma unroll
        for (int q = 0; q < 4; q++) O[j][q] = 0.0f;
    float m0 = -1e30f, m1 = -1e30f, l0 = 0.0f, l1 = 0.0f;
    uint32_t qfh[4][4], qfl[4][4];

    const int ktmax = 2 * qt + 1;
    const int r0g = qt * 128 + w * 16 + (lane >> 2);

    for (int kt = 0; kt <= ktmax; kt++) {
        if (kt + 1 <= ktmax) load_kv(kt + 1, (kt + 1) & 1);
        CP_COMMIT();
        CP_WAIT1();
        __syncthreads();

        if (kt == 0) {
            const uint32_t aq = (w * 16 + (lane & 15)) * AT_RS + ((lane >> 4) << 4);
            #pragma unroll
            for (int kk = 0; kk < 4; kk++) {
                ldsm_x4(qfh[kk], SQH + aq + kk * 32);
                ldsm_x4(qfl[kk], SQL + aq + kk * 32);
            }
        }

        const uint32_t kh_s = SKV + (kt & 1) * AT_STG;
        const uint32_t kl_s = kh_s + AT_KV_T;
        const uint32_t vh_s = kh_s + 2 * AT_KV_T;

        // ---- S = Q K^T (3-pass) ------------------------------------------
        float S[8][4];
        #pragma unroll
        for (int j = 0; j < 8; j++)
            #pragma unroll
            for (int q = 0; q < 4; q++) S[j][q] = 0.0f;

        const uint32_t brow = ((lane & 7) + ((lane >> 4) & 1) * 8) * AT_RS
                            + (((lane >> 3) & 1) << 4);
        #pragma unroll
        for (int kk = 0; kk < 4; kk++) {
            uint32_t bhf[8][2], blf[8][2];
            #pragma unroll
            for (int p = 0; p < 4; p++) {
                uint32_t t4[4];
                uint32_t ad = brow + p * 16 * AT_RS + kk * 32;
                ldsm_x4(t4, kh_s + ad);
                bhf[2 * p][0] = t4[0]; bhf[2 * p][1] = t4[1];
                bhf[2 * p + 1][0] = t4[2]; bhf[2 * p + 1][1] = t4[3];
                ldsm_x4(t4, kl_s + ad);
                blf[2 * p][0] = t4[0]; blf[2 * p][1] = t4[1];
                blf[2 * p + 1][0] = t4[2]; blf[2 * p + 1][1] = t4[3];
            }
            #pragma unroll
            for (int j = 0; j < 8; j++) {
                mma_bf16(S[j], qfh[kk], bhf[j]);
                mma_bf16(S[j], qfh[kk], blf[j]);
                mma_bf16(S[j], qfl[kk], bhf[j]);
            }
        }

        // ---- causal mask (only tiles kt >= 2*qt can cross the diagonal) --
        if (kt >= 2 * qt) {
            #pragma unroll
            for (int j = 0; j < 8; j++) {
                int key = kt * 64 + j * 8 + (lane & 3) * 2;
                if (key     > r0g)     S[j][0] = -1e30f;
                if (key + 1 > r0g)     S[j][1] = -1e30f;
                if (key     > r0g + 8) S[j][2] = -1e30f;
                if (key + 1 > r0g + 8) S[j][3] = -1e30f;
            }
        }

        // ---- online softmax ----------------------------------------------
        float mx0 = -1e30f, mx1 = -1e30f;
        #pragma unroll
        for (int j = 0; j < 8; j++) {
            mx0 = fmaxf(mx0, fmaxf(S[j][0], S[j][1]));
            mx1 = fmaxf(mx1, fmaxf(S[j][2], S[j][3]));
        }
        mx0 = fmaxf(mx0, __shfl_xor_sync(0xffffffffu, mx0, 1));
        mx0 = fmaxf(mx0, __shfl_xor_sync(0xffffffffu, mx0, 2));
        mx1 = fmaxf(mx1, __shfl_xor_sync(0xffffffffu, mx1, 1));
        mx1 = fmaxf(mx1, __shfl_xor_sync(0xffffffffu, mx1, 2));
        float mn0 = fmaxf(m0, mx0), mn1 = fmaxf(m1, mx1);
        float sc0 = __expf(m0 - mn0), sc1 = __expf(m1 - mn1);
        m0 = mn0; m1 = mn1;
        l0 *= sc0; l1 *= sc1;
        #pragma unroll
        for (int j = 0; j < 8; j++) {
            O[j][0] *= sc0; O[j][1] *= sc0; O[j][2] *= sc1; O[j][3] *= sc1;
            S[j][0] = __expf(S[j][0] - mn0);
            S[j][1] = __expf(S[j][1] - mn0);
            S[j][2] = __expf(S[j][2] - mn1);
            S[j][3] = __expf(S[j][3] - mn1);
            l0 += S[j][0] + S[j][1];
            l1 += S[j][2] + S[j][3];
        }

        // ---- O += P V (2-pass: Ph·Vh + Pl·Vh) ----------------------------
        #pragma unroll
        for (int kk = 0; kk < 4; kk++) {
            uint32_t ph[4], pl[4];
            #pragma unroll
            for (int u = 0; u < 2; u++) {
                int j = 2 * kk + u;
                __nv_bfloat162 hA, lA, hB, lB;
                split2(S[j][0], hA.x, lA.x); split2(S[j][1], hA.y, lA.y);
                split2(S[j][2], hB.x, lB.x); split2(S[j][3], hB.y, lB.y);
                ph[0 + u * 2] = *(uint32_t*)&hA;
                ph[1 + u * 2] = *(uint32_t*)&hB;
                pl[0 + u * 2] = *(uint32_t*)&lA;
                pl[1 + u * 2] = *(uint32_t*)&lB;
            }
            const uint32_t vrow = (kk * 16 + (lane & 15)) * AT_RS + ((lane >> 4) << 4);
            #pragma unroll
            for (int dp = 0; dp < 4; dp++) {
                uint32_t t4[4];
                uint32_t ad = vrow + dp * 32;
                ldsm_x4_t(t4, vh_s + ad);
                mma_bf16(O[2 * dp],     ph, t4);
                mma_bf16(O[2 * dp + 1], ph, t4 + 2);
                mma_bf16(O[2 * dp],     pl, t4);
                mma_bf16(O[2 * dp + 1], pl, t4 + 2);
            }
        }
        __syncthreads();
    }

    // ---- finalize + write y split bf16 -----------------------------------
    l0 += __shfl_xor_sync(0xffffffffu, l0, 1);
    l0 += __shfl_xor_sync(0xffffffffu, l0, 2);
    l1 += __shfl_xor_sync(0xffffffffu, l1, 1);
    l1 += __shfl_xor_sync(0xffffffffu, l1, 2);
    const float inv0 = 1.0f / l0, inv1 = 1.0f / l1;

    const size_t yb0 = (size_t)(b * TT + qt * 128 + w * 16 + (lane >> 2)) * CC + h * HD;
    const size_t yb1 = yb0 + (size_t)8 * CC;
    #pragma unroll
    for (int j = 0; j < 8; j++) {
        const int d = j * 8 + (lane & 3) * 2;
        __nv_bfloat162 hx, lx;
        split2(O[j][0] * inv0, hx.x, lx.x);
        split2(O[j][1] * inv0, hx.y, lx.y);
        *(__nv_bfloat162*)&yh[yb0 + d] = hx;
        *(__nv_bfloat162*)&yl[yb0 + d] = lx;
        split2(O[j][2] * inv1, hx.x, lx.x);
        split2(O[j][3] * inv1, hx.y, lx.y);
        *(__nv_bfloat162*)&yh[yb1 + d] = hx;
        *(__nv_bfloat162*)&yl[yb1 + d] = lx;
    }
}

// ---------------------------------------------------------------------------
extern "C" void kernel_launch(void* const* d_in, const int* in_sizes, int n_in,
                              void* d_out, int out_size)
{
    const float* x      = (const float*)d_in[0];
    const float* ln1_g  = (const float*)d_in[1];
    const float* ln1_b  = (const float*)d_in[2];
    const float* w_attn = (const float*)d_in[3];
    const float* b_attn = (const float*)d_in[4];
    const float* w_proj = (const float*)d_in[5];
    const float* b_proj = (const float*)d_in[6];
    const float* ln2_g  = (const float*)d_in[7];
    const float* ln2_b  = (const float*)d_in[8];
    const float* w_fc   = (const float*)d_in[9];
    const float* b_fc   = (const float*)d_in[10];
    const float* w_fc2  = (const float*)d_in[11];
    const float* b_fc2  = (const float*)d_in[12];
    float* out = (float*)d_out;

    float *x1p;
    __nv_bfloat16 *lnh, *lnl, *yh, *yl, *hh, *hl;
    __nv_bfloat16 *qh, *ql, *kh, *kl, *vh, *vl;
    __nv_bfloat16 *wah, *wal, *wph, *wpl, *wfh, *wfl, *w2h, *w2l;
    cudaGetSymbolAddress((void**)&x1p,  g_x1);
    cudaGetSymbolAddress((void**)&lnh,  g_lnh);  cudaGetSymbolAddress((void**)&lnl, g_lnl);
    cudaGetSymbolAddress((void**)&yh,   g_yh);   cudaGetSymbolAddress((void**)&yl,  g_yl);
    cudaGetSymbolAddress((void**)&hh,   g_hh);   cudaGetSymbolAddress((void**)&hl,  g_hl);
    cudaGetSymbolAddress((void**)&qh,   g_qh);   cudaGetSymbolAddress((void**)&ql,  g_ql);
    cudaGetSymbolAddress((void**)&kh,   g_kh);   cudaGetSymbolAddress((void**)&kl,  g_kl);
    cudaGetSymbolAddress((void**)&vh,   g_vh);   cudaGetSymbolAddress((void**)&vl,  g_vl);
    cudaGetSymbolAddress((void**)&wah,  g_wah);  cudaGetSymbolAddress((void**)&wal, g_wal);
    cudaGetSymbolAddress((void**)&wph,  g_wph);  cudaGetSymbolAddress((void**)&wpl, g_wpl);
    cudaGetSymbolAddress((void**)&wfh,  g_wfh);  cudaGetSymbolAddress((void**)&wfl, g_wfl);
    cudaGetSymbolAddress((void**)&w2h,  g_w2h);  cudaGetSymbolAddress((void**)&w2l, g_w2l);

    cudaFuncSetAttribute(gemm_tc<EPI_QKV>,       cudaFuncAttributeMaxDynamicSharedMemorySize, GEMM_SMEM_BYTES);
    cudaFuncSetAttribute(gemm_tc<EPI_F32_RES>,   cudaFuncAttributeMaxDynamicSharedMemorySize, GEMM_SMEM_BYTES);
    cudaFuncSetAttribute(gemm_tc<EPI_GELU_BF16>, cudaFuncAttributeMaxDynamicSharedMemorySize, GEMM_SMEM_BYTES);
    cudaFuncSetAttribute(attn_mma, cudaFuncAttributeMaxDynamicSharedMemorySize, AT_SMEM);

    const dim3 tb(32, 8);
    wsplit_t<<<dim3(3 * CC / 32, CC / 32), tb>>>(w_attn, wah, wal, CC, 3 * CC);
    wsplit_t<<<dim3(CC / 32, CC / 32), tb>>>(w_proj, wph, wpl, CC, CC);
    wsplit_t<<<dim3(4 * CC / 32, CC / 32), tb>>>(w_fc, wfh, wfl, CC, 4 * CC);
    wsplit_t<<<dim3(CC / 32, 4 * CC / 32), tb>>>(w_fc2, w2h, w2l, 4 * CC, CC);

    // 1) LN1
    ln_split<<<MM, 256>>>(x, ln1_g, ln1_b, lnh, lnl);
    // 2) qkv GEMM -> split q(scaled)/k/v bf16 in [bh][t][d]
    gemm_tc<EPI_QKV><<<dim3(3 * CC / 128, MM / 128), 256, GEMM_SMEM_BYTES>>>(
        lnh, lnl, wah, wal, b_attn, nullptr, nullptr, nullptr, nullptr,
        qh, ql, kh, kl, vh, vl, MM, 3 * CC, CC);
    // 3) HMMA flash attention -> y split
    attn_mma<<<dim3(TT / 128, BB * NH), 256, AT_SMEM>>>(qh, ql, kh, kl, vh, yh, yl);
    // 4) x1 = x + y @ w_proj + b_proj
    gemm_tc<EPI_F32_RES><<<dim3(CC / 128, MM / 128), 256, GEMM_SMEM_BYTES>>>(
        yh, yl, wph, wpl, b_proj, x, x1p, nullptr, nullptr,
        nullptr, nullptr, nullptr, nullptr, nullptr, nullptr, MM, CC, CC);
    // 5) LN2
    ln_split<<<MM, 256>>>(x1p, ln2_g, ln2_b, lnh, lnl);
    // 6) hfc = gelu(ln @ w_fc + b_fc) -> split bf16
    gemm_tc<EPI_GELU_BF16><<<dim3(4 * CC / 128, MM / 128), 256, GEMM_SMEM_BYTES>>>(
        lnh, lnl, wfh, wfl, b_fc, nullptr, nullptr, hh, hl,
        nullptr, nullptr, nullptr, nullptr, nullptr, nullptr, MM, 4 * CC, CC);
    // 7) out = x1 + hfc @ w_fc2 + b_fc2
    gemm_tc<EPI_F32_RES><<<dim3(CC / 128, MM / 128), 256, GEMM_SMEM_BYTES>>>(
        hh, hl, w2h, w2l, b_fc2, x1p, out, nullptr, nullptr,
        nullptr, nullptr, nullptr, nullptr, nullptr, nullptr, MM, CC, 4 * CC);
}